// round 16
// baseline (speedup 1.0000x reference)
#include <cuda_runtime.h>
#include <cuda_bf16.h>
#include <cuda_fp16.h>
#include <math.h>
#include <stdint.h>

#define N_NODES 16384
#define NGLOB   4
#define NTOTAL  (N_NODES + NGLOB)
#define DIM     256
#define HEADS   8
#define DHEAD   32
#define E_LOCAL 131072
#define E_EXP   65536
#define SLOT    96

// ---------------- scratch (static device allocations only) ----------------
__device__ __half g_qh [(size_t)NTOTAL * DIM];       // Q fp16
__device__ __half g_kvh[(size_t)NTOTAL * 2 * DIM];   // [row][k 256 | v 256] fp16
__device__ int    g_cnt[N_NODES];
__device__ int    g_srcbuf[(size_t)N_NODES * SLOT];
// GEMM operands
__device__ __half g_Ah[(size_t)NTOTAL * DIM];
__device__ __half g_Wh[(size_t)DIM * 768];
__device__ __half g_Wh2[(size_t)DIM * DIM];

// ---------------- helpers ----------------
__device__ __forceinline__ uint32_t smem_u32(const void* p) {
    return (uint32_t)__cvta_generic_to_shared(p);
}
__device__ __forceinline__ void cp_async16(uint32_t s, const void* g) {
    asm volatile("cp.async.cg.shared.global [%0], [%1], 16;" :: "r"(s), "l"(g));
}
__device__ __forceinline__ void ldsm_x4(uint32_t addr, uint32_t& r0, uint32_t& r1,
                                        uint32_t& r2, uint32_t& r3) {
    asm volatile("ldmatrix.sync.aligned.m8n8.x4.shared.b16 {%0,%1,%2,%3}, [%4];"
                 : "=r"(r0), "=r"(r1), "=r"(r2), "=r"(r3) : "r"(addr));
}
__device__ __forceinline__ void ldsm_x4_t(uint32_t addr, uint32_t& r0, uint32_t& r1,
                                          uint32_t& r2, uint32_t& r3) {
    asm volatile("ldmatrix.sync.aligned.m8n8.x4.trans.shared.b16 {%0,%1,%2,%3}, [%4];"
                 : "=r"(r0), "=r"(r1), "=r"(r2), "=r"(r3) : "r"(addr));
}
__device__ __forceinline__ void mma_f16(float* d, const uint32_t* a, const uint32_t* b) {
    asm volatile(
        "mma.sync.aligned.m16n8k16.row.col.f32.f16.f16.f32 "
        "{%0,%1,%2,%3},{%4,%5,%6,%7},{%8,%9},{%0,%1,%2,%3};"
        : "+f"(d[0]), "+f"(d[1]), "+f"(d[2]), "+f"(d[3])
        : "r"(a[0]), "r"(a[1]), "r"(a[2]), "r"(a[3]), "r"(b[0]), "r"(b[1]));
}

// ---------------- bucketed adjacency build ----------------
__global__ void zero_cnt_kernel() {
    int t = blockIdx.x * blockDim.x + threadIdx.x;
    if (t < N_NODES) g_cnt[t] = 0;
}

__global__ void fill_kernel(const int* __restrict__ ei, const int* __restrict__ xi) {
    int t = blockIdx.x * blockDim.x + threadIdx.x;
    if (t < E_LOCAL) {
        int d = ei[E_LOCAL + t];
        int p = atomicAdd(&g_cnt[d], 1);
        g_srcbuf[(size_t)d * SLOT + p] = ei[t];
    }
    if (t < E_EXP) {
        int d = xi[E_EXP + t];
        int p = atomicAdd(&g_cnt[d], 1);
        g_srcbuf[(size_t)d * SLOT + p] = xi[t];
    }
}

// ---------------- conversion: fp32 -> fp16 ----------------
__global__ void tohalf_kernel(const float* __restrict__ src,
                              __half* __restrict__ dst, int n2) {
    int t = blockIdx.x * blockDim.x + threadIdx.x;
    if (t >= n2) return;
    float2 v = ((const float2*)src)[t];
    ((__half2*)dst)[t] = __float22half2_rn(v);
}

// ---------------- fp16 tensor-core GEMM (3-stage, persistent tiles) ----------------
#define AS_STRIDE 40
#define BS_STRIDE 136
#define STAGE_ELEMS (128 * AS_STRIDE + 32 * BS_STRIDE)
#define AS_OFF(buf) ((buf) * STAGE_ELEMS)
#define BS_OFF(buf) ((buf) * STAGE_ELEMS + 128 * AS_STRIDE)
#define GEMM_SMEM_ELEMS (3 * STAGE_ELEMS)
#define GEMM_SMEM_BYTES (GEMM_SMEM_ELEMS * 2)

// QKV mode (qh != nullptr): cols <256 -> fp16 qh; cols >=256 -> fp16 kvh.
// Plain mode (qh == nullptr): fp32 C.
__global__ __launch_bounds__(256) void gemm_tc_kernel(
    const __half* __restrict__ Ah, const __half* __restrict__ Wh,
    const float* __restrict__ bias, float* __restrict__ C, int M, int Ncols,
    __half* __restrict__ qh, __half* __restrict__ kvh,
    int nTiles, int nTileX)
{
    extern __shared__ __half sm[];
    const int tid    = threadIdx.x;
    const int lane   = tid & 31;
    const int warp   = tid >> 5;
    const int warp_m = warp & 3;       // 4 x 32 rows
    const int warp_n = warp >> 2;      // 2 x 64 cols

    const int fa_row  = warp_m * 32 + (lane & 15);
    const int fa_koff = (lane >> 4) << 3;
    const int fb_krow = (((lane >> 3) & 1) << 3) + (lane & 7);
    const int fb_n    = warp_n * 64 + ((lane >> 4) << 3);

    for (int tile = blockIdx.x; tile < nTiles; tile += gridDim.x) {
        const int row0 = (tile / nTileX) * 128;
        const int col0 = (tile % nTileX) * 128;

        if (tile != (int)blockIdx.x) __syncthreads();   // protect smem reuse

        float acc[2][8][4];
#pragma unroll
        for (int i = 0; i < 2; i++)
#pragma unroll
            for (int j = 0; j < 8; j++)
#pragma unroll
                for (int q = 0; q < 4; q++) acc[i][j][q] = 0.f;

        auto load_stage = [&](int kt, int buf) {
            const int k0 = kt * 32;
#pragma unroll
            for (int i = 0; i < 2; i++) {
                int c  = tid * 2 + i;          // [0,512)
                int r  = c >> 2;
                int kk = (c & 3) * 8;
                int gr = row0 + r; if (gr >= M) gr = M - 1;
                cp_async16(smem_u32(&sm[AS_OFF(buf) + r * AS_STRIDE + kk]),
                           Ah + (size_t)gr * DIM + k0 + kk);
            }
#pragma unroll
            for (int i = 0; i < 2; i++) {
                int c  = tid * 2 + i;          // [0,512)
                int k  = c >> 4;
                int nn = (c & 15) * 8;
                cp_async16(smem_u32(&sm[BS_OFF(buf) + k * BS_STRIDE + nn]),
                           Wh + (size_t)(k0 + k) * Ncols + col0 + nn);
            }
            asm volatile("cp.async.commit_group;" ::: "memory");
        };

        load_stage(0, 0);
        load_stage(1, 1);

#pragma unroll
        for (int kt = 0; kt < 8; kt++) {
            const int buf = kt % 3;
            if (kt == 7) asm volatile("cp.async.wait_group 0;" ::: "memory");
            else         asm volatile("cp.async.wait_group 1;" ::: "memory");
            __syncthreads();
            if (kt < 6) load_stage(kt + 2, (kt + 2) % 3);

#pragma unroll
            for (int ks = 0; ks < 32; ks += 16) {
                uint32_t ah[2][4], bh[8][2];
#pragma unroll
                for (int mt = 0; mt < 2; mt++)
                    ldsm_x4(smem_u32(&sm[AS_OFF(buf) + (fa_row + mt*16) * AS_STRIDE + ks + fa_koff]),
                            ah[mt][0], ah[mt][1], ah[mt][2], ah[mt][3]);
#pragma unroll
                for (int np = 0; np < 4; np++)
                    ldsm_x4_t(smem_u32(&sm[BS_OFF(buf) + (ks + fb_krow) * BS_STRIDE + fb_n + np*16]),
                              bh[np*2][0], bh[np*2][1], bh[np*2+1][0], bh[np*2+1][1]);
#pragma unroll
                for (int mt = 0; mt < 2; mt++)
#pragma unroll
                    for (int nt = 0; nt < 8; nt++)
                        mma_f16(acc[mt][nt], ah[mt], bh[nt]);
            }
        }

        // epilogue
#pragma unroll
        for (int mt = 0; mt < 2; mt++) {
            int r_base = row0 + warp_m * 32 + mt * 16 + (lane >> 2);
#pragma unroll
            for (int nt = 0; nt < 8; nt++) {
                int c = col0 + warp_n * 64 + nt * 8 + (lane & 3) * 2;
                float b0 = bias[c], b1 = bias[c + 1];
                if (qh != nullptr) {
                    if (r_base < M) {
                        __half2 v = __float22half2_rn(
                            make_float2(acc[mt][nt][0] + b0, acc[mt][nt][1] + b1));
                        if (c >= 256) *(__half2*)&kvh[(size_t)r_base * 512 + (c - 256)] = v;
                        else          *(__half2*)&qh[(size_t)r_base * 256 + c] = v;
                    }
                    if (r_base + 8 < M) {
                        __half2 v = __float22half2_rn(
                            make_float2(acc[mt][nt][2] + b0, acc[mt][nt][3] + b1));
                        if (c >= 256) *(__half2*)&kvh[(size_t)(r_base + 8) * 512 + (c - 256)] = v;
                        else          *(__half2*)&qh[(size_t)(r_base + 8) * 256 + c] = v;
                    }
                } else {
                    if (r_base < M) {
                        float2 v = make_float2(acc[mt][nt][0] + b0, acc[mt][nt][1] + b1);
                        *(float2*)&C[(size_t)r_base * Ncols + c] = v;
                    }
                    if (r_base + 8 < M) {
                        float2 v = make_float2(acc[mt][nt][2] + b0, acc[mt][nt][3] + b1);
                        *(float2*)&C[(size_t)(r_base + 8) * Ncols + c] = v;
                    }
                }
            }
        }
    }
}

// ---------------- attention: one warp per dst node, K/V prefetch pipeline ----------------
__global__ __launch_bounds__(256) void attn_kernel() {
    int gw = (blockIdx.x * blockDim.x + threadIdx.x) >> 5;
    if (gw >= N_NODES) return;
    const int lane = threadIdx.x & 31;           // lane = head*4 + quarter
    const float scale = 0.17677669529663687f;    // 32^-0.5

    float q[8];
    {
        uint4 qraw = *(const uint4*)(g_qh + (size_t)gw * 256 + (lane << 3));
        __half2 qh0 = *(__half2*)&qraw.x, qh1 = *(__half2*)&qraw.y;
        __half2 qh2 = *(__half2*)&qraw.z, qh3 = *(__half2*)&qraw.w;
        float2 a = __half22float2(qh0), b = __half22float2(qh1);
        float2 c = __half22float2(qh2), d = __half22float2(qh3);
        q[0] = a.x * scale; q[1] = a.y * scale; q[2] = b.x * scale; q[3] = b.y * scale;
        q[4] = c.x * scale; q[5] = c.y * scale; q[6] = d.x * scale; q[7] = d.y * scale;
    }

    float m = -INFINITY, l = 0.f;
    float acc[8];
#pragma unroll
    for (int i = 0; i < 8; i++) acc[i] = 0.f;

    const size_t s0  = (size_t)gw * SLOT;
    const int   nloc = g_cnt[gw];
    const int   ntot = nloc + 1 + NGLOB;

    int src0 = (0 < nloc) ? g_srcbuf[s0] : gw;
    const __half* Kp0 = g_kvh + (size_t)src0 * 512 + (lane << 3);
    uint4 kraw = *(const uint4*)Kp0;
    uint4 vraw = *(const uint4*)(Kp0 + 256);

    for (int it = 0; it < ntot; it++) {
        uint4 knext = kraw, vnext = vraw;
        if (it + 1 < ntot) {
            int it1 = it + 1;
            int nsrc;
            if (it1 < nloc)       nsrc = g_srcbuf[s0 + it1];
            else if (it1 == nloc) nsrc = gw;
            else                  nsrc = N_NODES + (it1 - nloc - 1);
            const __half* Kn = g_kvh + (size_t)nsrc * 512 + (lane << 3);
            knext = *(const uint4*)Kn;
            vnext = *(const uint4*)(Kn + 256);
        }

        __half2 kh0 = *(__half2*)&kraw.x, kh1 = *(__half2*)&kraw.y;
        __half2 kh2 = *(__half2*)&kraw.z, kh3 = *(__half2*)&kraw.w;
        float2 k0 = __half22float2(kh0), k1 = __half22float2(kh1);
        float2 k2 = __half22float2(kh2), k3 = __half22float2(kh3);
        float dot = q[0]*k0.x + q[1]*k0.y + q[2]*k1.x + q[3]*k1.y
                  + q[4]*k2.x + q[5]*k2.y + q[6]*k3.x + q[7]*k3.y;
        dot += __shfl_xor_sync(0xFFFFFFFFu, dot, 1);
        dot += __shfl_xor_sync(0xFFFFFFFFu, dot, 2);

        float mnew = fmaxf(m, dot);
        float corr = __expf(m - mnew);
        float w    = __expf(dot - mnew);
        l = l * corr + w;

        __half2 vh0 = *(__half2*)&vraw.x, vh1 = *(__half2*)&vraw.y;
        __half2 vh2 = *(__half2*)&vraw.z, vh3 = *(__half2*)&vraw.w;
        float2 v0 = __half22float2(vh0), v1 = __half22float2(vh1);
        float2 v2 = __half22float2(vh2), v3 = __half22float2(vh3);
        acc[0] = acc[0] * corr + w * v0.x;
        acc[1] = acc[1] * corr + w * v0.y;
        acc[2] = acc[2] * corr + w * v1.x;
        acc[3] = acc[3] * corr + w * v1.y;
        acc[4] = acc[4] * corr + w * v2.x;
        acc[5] = acc[5] * corr + w * v2.y;
        acc[6] = acc[6] * corr + w * v3.x;
        acc[7] = acc[7] * corr + w * v3.y;
        m = mnew;

        kraw = knext; vraw = vnext;
    }

    float inv = 1.f / l;
    union { __half2 h2[4]; uint4 u; } H;
#pragma unroll
    for (int i = 0; i < 4; i++)
        H.h2[i] = __float22half2_rn(make_float2(acc[2*i] * inv, acc[2*i+1] * inv));
    *(uint4*)&g_Ah[(size_t)gw * 256 + (lane << 3)] = H.u;
}

// ---------------- launch ----------------
extern "C" void kernel_launch(void* const* d_in, const int* in_sizes, int n_in,
                              void* d_out, int out_size) {
    const float* x      = (const float*)d_in[0];
    const int*   ei     = (const int*)d_in[1];
    const int*   xi     = (const int*)d_in[2];
    const float* W_qkv  = (const float*)d_in[3];
    const float* b_qkv  = (const float*)d_in[4];
    const float* W_out  = (const float*)d_in[5];
    const float* b_out  = (const float*)d_in[6];
    const float* gtok   = (const float*)d_in[7];
    float* out = (float*)d_out;

    __half* qh_ptr;   cudaGetSymbolAddress((void**)&qh_ptr,  g_qh);
    __half* kvh_ptr;  cudaGetSymbolAddress((void**)&kvh_ptr, g_kvh);
    __half *Ah, *Wh, *Wh2;
    cudaGetSymbolAddress((void**)&Ah,  g_Ah);
    cudaGetSymbolAddress((void**)&Wh,  g_Wh);
    cudaGetSymbolAddress((void**)&Wh2, g_Wh2);

    // one-time resources (created on the uncaptured correctness call)
    static cudaStream_t s2 = nullptr;
    static cudaEvent_t evFork = nullptr, evW = nullptr, evJoin = nullptr;
    if (!s2) {
        cudaStreamCreateWithFlags(&s2, cudaStreamNonBlocking);
        cudaEventCreateWithFlags(&evFork, cudaEventDisableTiming);
        cudaEventCreateWithFlags(&evW,    cudaEventDisableTiming);
        cudaEventCreateWithFlags(&evJoin, cudaEventDisableTiming);
        cudaFuncSetAttribute(gemm_tc_kernel,
                             cudaFuncAttributeMaxDynamicSharedMemorySize, GEMM_SMEM_BYTES);
    }

    // fork side stream from the captured (default) stream
    cudaEventRecord(evFork, 0);
    cudaStreamWaitEvent(s2, evFork, 0);

    // side stream: W_qkv conversion first (needed by GEMM1), then buckets + W_out
    tohalf_kernel<<<(DIM * 768 / 2 + 255) / 256, 256, 0, s2>>>(W_qkv, Wh, DIM * 768 / 2);
    cudaEventRecord(evW, s2);
    zero_cnt_kernel<<<N_NODES / 256, 256, 0, s2>>>();
    fill_kernel<<<(E_LOCAL + 255) / 256, 256, 0, s2>>>(ei, xi);
    tohalf_kernel<<<(DIM * DIM / 2 + 255) / 256, 256, 0, s2>>>(W_out, Wh2, DIM * DIM / 2);
    cudaEventRecord(evJoin, s2);

    // main stream: x/gtok conversions (overlap with W conversion)
    tohalf_kernel<<<(N_NODES * DIM / 2 + 255) / 256, 256>>>(x, Ah, N_NODES * DIM / 2);
    tohalf_kernel<<<2, 256>>>(gtok, Ah + (size_t)N_NODES * DIM, NGLOB * DIM / 2);
    cudaStreamWaitEvent(0, evW, 0);

    // QKV projection: persistent tiles (774 tiles = 258 CTAs x 3, single wave)
    gemm_tc_kernel<<<258, 256, GEMM_SMEM_BYTES>>>(Ah, Wh, b_qkv, nullptr, NTOTAL, 768,
                                                  qh_ptr, kvh_ptr, 774, 6);

    // join: attention needs buckets (side stream) + QKV (main stream)
    cudaStreamWaitEvent(0, evJoin, 0);

    attn_kernel<<<(N_NODES * 32) / 256, 256>>>();

    // out projection: 256 tiles, 1 per CTA
    gemm_tc_kernel<<<256, 256, GEMM_SMEM_BYTES>>>(Ah, Wh2, b_out, out, N_NODES, 256,
                                                  nullptr, nullptr, 256, 2);
}

// round 17
// speedup vs baseline: 1.0827x; 1.0827x over previous
#include <cuda_runtime.h>
#include <cuda_bf16.h>
#include <cuda_fp16.h>
#include <math.h>
#include <stdint.h>

#define N_NODES 16384
#define NGLOB   4
#define NTOTAL  (N_NODES + NGLOB)
#define DIM     256
#define HEADS   8
#define DHEAD   32
#define E_LOCAL 131072
#define E_EXP   65536
#define SLOT    96

// ---------------- scratch (static device allocations only) ----------------
__device__ __half g_qh [(size_t)NTOTAL * DIM];       // Q fp16
__device__ __half g_kvh[(size_t)NTOTAL * 2 * DIM];   // [row][k 256 | v 256] fp16
__device__ int    g_cnt[N_NODES];
__device__ int    g_srcbuf[(size_t)N_NODES * SLOT];
// GEMM operands
__device__ __half g_Ah[(size_t)NTOTAL * DIM];
__device__ __half g_Wh[(size_t)DIM * 768];
__device__ __half g_Wh2[(size_t)DIM * DIM];

// ---------------- helpers ----------------
__device__ __forceinline__ uint32_t smem_u32(const void* p) {
    return (uint32_t)__cvta_generic_to_shared(p);
}
__device__ __forceinline__ void cp_async16(uint32_t s, const void* g) {
    asm volatile("cp.async.cg.shared.global [%0], [%1], 16;" :: "r"(s), "l"(g));
}
__device__ __forceinline__ void ldsm_x4(uint32_t addr, uint32_t& r0, uint32_t& r1,
                                        uint32_t& r2, uint32_t& r3) {
    asm volatile("ldmatrix.sync.aligned.m8n8.x4.shared.b16 {%0,%1,%2,%3}, [%4];"
                 : "=r"(r0), "=r"(r1), "=r"(r2), "=r"(r3) : "r"(addr));
}
__device__ __forceinline__ void ldsm_x4_t(uint32_t addr, uint32_t& r0, uint32_t& r1,
                                          uint32_t& r2, uint32_t& r3) {
    asm volatile("ldmatrix.sync.aligned.m8n8.x4.trans.shared.b16 {%0,%1,%2,%3}, [%4];"
                 : "=r"(r0), "=r"(r1), "=r"(r2), "=r"(r3) : "r"(addr));
}
__device__ __forceinline__ void mma_f16(float* d, const uint32_t* a, const uint32_t* b) {
    asm volatile(
        "mma.sync.aligned.m16n8k16.row.col.f32.f16.f16.f32 "
        "{%0,%1,%2,%3},{%4,%5,%6,%7},{%8,%9},{%0,%1,%2,%3};"
        : "+f"(d[0]), "+f"(d[1]), "+f"(d[2]), "+f"(d[3])
        : "r"(a[0]), "r"(a[1]), "r"(a[2]), "r"(a[3]), "r"(b[0]), "r"(b[1]));
}

// ---------------- bucketed adjacency build ----------------
__global__ void zero_cnt_kernel() {
    int t = blockIdx.x * blockDim.x + threadIdx.x;
    if (t < N_NODES) g_cnt[t] = 0;
}

__global__ void fill_kernel(const int* __restrict__ ei, const int* __restrict__ xi) {
    int t = blockIdx.x * blockDim.x + threadIdx.x;
    if (t < E_LOCAL) {
        int d = ei[E_LOCAL + t];
        int p = atomicAdd(&g_cnt[d], 1);
        g_srcbuf[(size_t)d * SLOT + p] = ei[t];
    }
    if (t < E_EXP) {
        int d = xi[E_EXP + t];
        int p = atomicAdd(&g_cnt[d], 1);
        g_srcbuf[(size_t)d * SLOT + p] = xi[t];
    }
}

// ---------------- conversion: fp32 -> fp16 ----------------
__global__ void tohalf_kernel(const float* __restrict__ src,
                              __half* __restrict__ dst, int n2) {
    int t = blockIdx.x * blockDim.x + threadIdx.x;
    if (t >= n2) return;
    float2 v = ((const float2*)src)[t];
    ((__half2*)dst)[t] = __float22half2_rn(v);
}

// ---------------- fp16 tensor-core GEMM (3-stage, single barrier/iter) ----------------
#define AS_STRIDE 40
#define BS_STRIDE 136
#define STAGE_ELEMS (128 * AS_STRIDE + 32 * BS_STRIDE)
#define AS_OFF(buf) ((buf) * STAGE_ELEMS)
#define BS_OFF(buf) ((buf) * STAGE_ELEMS + 128 * AS_STRIDE)
#define GEMM_SMEM_ELEMS (3 * STAGE_ELEMS)
#define GEMM_SMEM_BYTES (GEMM_SMEM_ELEMS * 2)

// QKV mode (qh != nullptr): cols <256 -> fp16 qh; cols >=256 -> fp16 kvh.
// Plain mode (qh == nullptr): fp32 C.
__global__ __launch_bounds__(256) void gemm_tc_kernel(
    const __half* __restrict__ Ah, const __half* __restrict__ Wh,
    const float* __restrict__ bias, float* __restrict__ C, int M, int Ncols,
    __half* __restrict__ qh, __half* __restrict__ kvh)
{
    extern __shared__ __half sm[];
    const int tid    = threadIdx.x;
    const int lane   = tid & 31;
    const int warp   = tid >> 5;
    const int warp_m = warp & 3;       // 4 x 32 rows
    const int warp_n = warp >> 2;      // 2 x 64 cols
    const int row0   = blockIdx.y * 128;
    const int col0   = blockIdx.x * 128;

    float acc[2][8][4];
#pragma unroll
    for (int i = 0; i < 2; i++)
#pragma unroll
        for (int j = 0; j < 8; j++)
#pragma unroll
            for (int q = 0; q < 4; q++) acc[i][j][q] = 0.f;

    const int fa_row  = warp_m * 32 + (lane & 15);
    const int fa_koff = (lane >> 4) << 3;
    const int fb_krow = (((lane >> 3) & 1) << 3) + (lane & 7);
    const int fb_n    = warp_n * 64 + ((lane >> 4) << 3);

    auto load_stage = [&](int kt, int buf) {
        const int k0 = kt * 32;
#pragma unroll
        for (int i = 0; i < 2; i++) {
            int c  = tid * 2 + i;          // [0,512)
            int r  = c >> 2;
            int kk = (c & 3) * 8;
            int gr = row0 + r; if (gr >= M) gr = M - 1;
            cp_async16(smem_u32(&sm[AS_OFF(buf) + r * AS_STRIDE + kk]),
                       Ah + (size_t)gr * DIM + k0 + kk);
        }
#pragma unroll
        for (int i = 0; i < 2; i++) {
            int c  = tid * 2 + i;          // [0,512)
            int k  = c >> 4;
            int nn = (c & 15) * 8;
            cp_async16(smem_u32(&sm[BS_OFF(buf) + k * BS_STRIDE + nn]),
                       Wh + (size_t)(k0 + k) * Ncols + col0 + nn);
        }
        asm volatile("cp.async.commit_group;" ::: "memory");
    };

    load_stage(0, 0);
    load_stage(1, 1);

#pragma unroll
    for (int kt = 0; kt < 8; kt++) {
        const int buf = kt % 3;
        if (kt == 7) asm volatile("cp.async.wait_group 0;" ::: "memory");
        else         asm volatile("cp.async.wait_group 1;" ::: "memory");
        __syncthreads();
        if (kt < 6) load_stage(kt + 2, (kt + 2) % 3);

#pragma unroll
        for (int ks = 0; ks < 32; ks += 16) {
            uint32_t ah[2][4], bh[8][2];
#pragma unroll
            for (int mt = 0; mt < 2; mt++)
                ldsm_x4(smem_u32(&sm[AS_OFF(buf) + (fa_row + mt*16) * AS_STRIDE + ks + fa_koff]),
                        ah[mt][0], ah[mt][1], ah[mt][2], ah[mt][3]);
#pragma unroll
            for (int np = 0; np < 4; np++)
                ldsm_x4_t(smem_u32(&sm[BS_OFF(buf) + (ks + fb_krow) * BS_STRIDE + fb_n + np*16]),
                          bh[np*2][0], bh[np*2][1], bh[np*2+1][0], bh[np*2+1][1]);
#pragma unroll
            for (int mt = 0; mt < 2; mt++)
#pragma unroll
                for (int nt = 0; nt < 8; nt++)
                    mma_f16(acc[mt][nt], ah[mt], bh[nt]);
        }
    }

    // epilogue
#pragma unroll
    for (int mt = 0; mt < 2; mt++) {
        int r_base = row0 + warp_m * 32 + mt * 16 + (lane >> 2);
#pragma unroll
        for (int nt = 0; nt < 8; nt++) {
            int c = col0 + warp_n * 64 + nt * 8 + (lane & 3) * 2;
            float b0 = bias[c], b1 = bias[c + 1];
            if (qh != nullptr) {
                if (r_base < M) {
                    __half2 v = __float22half2_rn(
                        make_float2(acc[mt][nt][0] + b0, acc[mt][nt][1] + b1));
                    if (c >= 256) *(__half2*)&kvh[(size_t)r_base * 512 + (c - 256)] = v;
                    else          *(__half2*)&qh[(size_t)r_base * 256 + c] = v;
                }
                if (r_base + 8 < M) {
                    __half2 v = __float22half2_rn(
                        make_float2(acc[mt][nt][2] + b0, acc[mt][nt][3] + b1));
                    if (c >= 256) *(__half2*)&kvh[(size_t)(r_base + 8) * 512 + (c - 256)] = v;
                    else          *(__half2*)&qh[(size_t)(r_base + 8) * 256 + c] = v;
                }
            } else {
                if (r_base < M) {
                    float2 v = make_float2(acc[mt][nt][0] + b0, acc[mt][nt][1] + b1);
                    *(float2*)&C[(size_t)r_base * Ncols + c] = v;
                }
                if (r_base + 8 < M) {
                    float2 v = make_float2(acc[mt][nt][2] + b0, acc[mt][nt][3] + b1);
                    *(float2*)&C[(size_t)(r_base + 8) * Ncols + c] = v;
                }
            }
        }
    }
}

// ---------------- attention: one warp per dst node, K/V prefetch pipeline ----------------
__global__ __launch_bounds__(256) void attn_kernel() {
    int gw = (blockIdx.x * blockDim.x + threadIdx.x) >> 5;
    if (gw >= N_NODES) return;
    const int lane = threadIdx.x & 31;           // lane = head*4 + quarter
    const float scale = 0.17677669529663687f;    // 32^-0.5

    float q[8];
    {
        uint4 qraw = *(const uint4*)(g_qh + (size_t)gw * 256 + (lane << 3));
        __half2 qh0 = *(__half2*)&qraw.x, qh1 = *(__half2*)&qraw.y;
        __half2 qh2 = *(__half2*)&qraw.z, qh3 = *(__half2*)&qraw.w;
        float2 a = __half22float2(qh0), b = __half22float2(qh1);
        float2 c = __half22float2(qh2), d = __half22float2(qh3);
        q[0] = a.x * scale; q[1] = a.y * scale; q[2] = b.x * scale; q[3] = b.y * scale;
        q[4] = c.x * scale; q[5] = c.y * scale; q[6] = d.x * scale; q[7] = d.y * scale;
    }

    float m = -INFINITY, l = 0.f;
    float acc[8];
#pragma unroll
    for (int i = 0; i < 8; i++) acc[i] = 0.f;

    const size_t s0  = (size_t)gw * SLOT;
    const int   nloc = g_cnt[gw];
    const int   ntot = nloc + 1 + NGLOB;

    int src0 = (0 < nloc) ? g_srcbuf[s0] : gw;
    const __half* Kp0 = g_kvh + (size_t)src0 * 512 + (lane << 3);
    uint4 kraw = *(const uint4*)Kp0;
    uint4 vraw = *(const uint4*)(Kp0 + 256);

    for (int it = 0; it < ntot; it++) {
        uint4 knext = kraw, vnext = vraw;
        if (it + 1 < ntot) {
            int it1 = it + 1;
            int nsrc;
            if (it1 < nloc)       nsrc = g_srcbuf[s0 + it1];
            else if (it1 == nloc) nsrc = gw;
            else                  nsrc = N_NODES + (it1 - nloc - 1);
            const __half* Kn = g_kvh + (size_t)nsrc * 512 + (lane << 3);
            knext = *(const uint4*)Kn;
            vnext = *(const uint4*)(Kn + 256);
        }

        __half2 kh0 = *(__half2*)&kraw.x, kh1 = *(__half2*)&kraw.y;
        __half2 kh2 = *(__half2*)&kraw.z, kh3 = *(__half2*)&kraw.w;
        float2 k0 = __half22float2(kh0), k1 = __half22float2(kh1);
        float2 k2 = __half22float2(kh2), k3 = __half22float2(kh3);
        float dot = q[0]*k0.x + q[1]*k0.y + q[2]*k1.x + q[3]*k1.y
                  + q[4]*k2.x + q[5]*k2.y + q[6]*k3.x + q[7]*k3.y;
        dot += __shfl_xor_sync(0xFFFFFFFFu, dot, 1);
        dot += __shfl_xor_sync(0xFFFFFFFFu, dot, 2);

        float mnew = fmaxf(m, dot);
        float corr = __expf(m - mnew);
        float w    = __expf(dot - mnew);
        l = l * corr + w;

        __half2 vh0 = *(__half2*)&vraw.x, vh1 = *(__half2*)&vraw.y;
        __half2 vh2 = *(__half2*)&vraw.z, vh3 = *(__half2*)&vraw.w;
        float2 v0 = __half22float2(vh0), v1 = __half22float2(vh1);
        float2 v2 = __half22float2(vh2), v3 = __half22float2(vh3);
        acc[0] = acc[0] * corr + w * v0.x;
        acc[1] = acc[1] * corr + w * v0.y;
        acc[2] = acc[2] * corr + w * v1.x;
        acc[3] = acc[3] * corr + w * v1.y;
        acc[4] = acc[4] * corr + w * v2.x;
        acc[5] = acc[5] * corr + w * v2.y;
        acc[6] = acc[6] * corr + w * v3.x;
        acc[7] = acc[7] * corr + w * v3.y;
        m = mnew;

        kraw = knext; vraw = vnext;
    }

    float inv = 1.f / l;
    union { __half2 h2[4]; uint4 u; } H;
#pragma unroll
    for (int i = 0; i < 4; i++)
        H.h2[i] = __float22half2_rn(make_float2(acc[2*i] * inv, acc[2*i+1] * inv));
    *(uint4*)&g_Ah[(size_t)gw * 256 + (lane << 3)] = H.u;
}

// ---------------- launch ----------------
extern "C" void kernel_launch(void* const* d_in, const int* in_sizes, int n_in,
                              void* d_out, int out_size) {
    const float* x      = (const float*)d_in[0];
    const int*   ei     = (const int*)d_in[1];
    const int*   xi     = (const int*)d_in[2];
    const float* W_qkv  = (const float*)d_in[3];
    const float* b_qkv  = (const float*)d_in[4];
    const float* W_out  = (const float*)d_in[5];
    const float* b_out  = (const float*)d_in[6];
    const float* gtok   = (const float*)d_in[7];
    float* out = (float*)d_out;

    __half* qh_ptr;   cudaGetSymbolAddress((void**)&qh_ptr,  g_qh);
    __half* kvh_ptr;  cudaGetSymbolAddress((void**)&kvh_ptr, g_kvh);
    __half *Ah, *Wh, *Wh2;
    cudaGetSymbolAddress((void**)&Ah,  g_Ah);
    cudaGetSymbolAddress((void**)&Wh,  g_Wh);
    cudaGetSymbolAddress((void**)&Wh2, g_Wh2);

    // one-time resources (created on the uncaptured correctness call)
    static cudaStream_t s2 = nullptr;
    static cudaEvent_t evFork = nullptr, evW = nullptr, evJoin = nullptr;
    if (!s2) {
        cudaStreamCreateWithFlags(&s2, cudaStreamNonBlocking);
        cudaEventCreateWithFlags(&evFork, cudaEventDisableTiming);
        cudaEventCreateWithFlags(&evW,    cudaEventDisableTiming);
        cudaEventCreateWithFlags(&evJoin, cudaEventDisableTiming);
        cudaFuncSetAttribute(gemm_tc_kernel,
                             cudaFuncAttributeMaxDynamicSharedMemorySize, GEMM_SMEM_BYTES);
    }

    // fork side stream from the captured (default) stream
    cudaEventRecord(evFork, 0);
    cudaStreamWaitEvent(s2, evFork, 0);

    // side stream: W_qkv conversion first (needed by GEMM1), then buckets + W_out
    tohalf_kernel<<<(DIM * 768 / 2 + 255) / 256, 256, 0, s2>>>(W_qkv, Wh, DIM * 768 / 2);
    cudaEventRecord(evW, s2);
    zero_cnt_kernel<<<N_NODES / 256, 256, 0, s2>>>();
    fill_kernel<<<(E_LOCAL + 255) / 256, 256, 0, s2>>>(ei, xi);
    tohalf_kernel<<<(DIM * DIM / 2 + 255) / 256, 256, 0, s2>>>(W_out, Wh2, DIM * DIM / 2);
    cudaEventRecord(evJoin, s2);

    // main stream: x/gtok conversions (overlap with W conversion)
    tohalf_kernel<<<(N_NODES * DIM / 2 + 255) / 256, 256>>>(x, Ah, N_NODES * DIM / 2);
    tohalf_kernel<<<2, 256>>>(gtok, Ah + (size_t)N_NODES * DIM, NGLOB * DIM / 2);
    cudaStreamWaitEvent(0, evW, 0);

    // QKV projection: Q -> fp16 g_qh, K/V -> fp16 g_kvh
    {
        dim3 grid(768 / 128, (NTOTAL + 127) / 128);
        gemm_tc_kernel<<<grid, 256, GEMM_SMEM_BYTES>>>(Ah, Wh, b_qkv, nullptr,
                                                       NTOTAL, 768, qh_ptr, kvh_ptr);
    }

    // join: attention needs buckets (side stream) + QKV (main stream)
    cudaStreamWaitEvent(0, evJoin, 0);

    attn_kernel<<<(N_NODES * 32) / 256, 256>>>();

    // out projection: [16384, 256] x [256, 256] + b
    {
        dim3 grid(256 / 128, N_NODES / 128);
        gemm_tc_kernel<<<grid, 256, GEMM_SMEM_BYTES>>>(Ah, Wh2, b_out, out,
                                                       N_NODES, 256, nullptr, nullptr);
    }
}